// round 7
// baseline (speedup 1.0000x reference)
#include <cuda_runtime.h>
#include <math.h>

#define NB 32
#define NA 8400
#define NG 100
#define BA (NB*NA)
#define NBLK 148
#define NTHR 256
#define NTILE (33*32)   // 256-anchor tiles: 33 per image x 32 images

// ---- device scratch (static globals; zero-initialized at load) ----
__device__ int    g_cnt[BA];
__device__ float  g_miou[BA];
__device__ int    g_nfg[NB];        // reset by block 0 at end of each run
__device__ int    g_cidx[BA];
__device__ float4 g_cbox[BA];
__device__ float4 g_cgeo[BA];
__device__ float  g_psum[NBLK];
__device__ int    g_pcnt[NBLK];
__device__ volatile int g_bar_gen;  // grid barrier generation (monotonic)
__device__ int    g_bar_cnt;

__device__ __forceinline__ float softplus(float x){
    return fmaxf(x, 0.0f) + log1pf(expf(-fabsf(x)));
}

__device__ __forceinline__ void gridbar(){
    __syncthreads();
    __threadfence();
    if (threadIdx.x == 0){
        int gen = g_bar_gen;
        if (atomicAdd(&g_bar_cnt, 1) == NBLK - 1){
            g_bar_cnt = 0;
            __threadfence();
            g_bar_gen = gen + 1;
        } else {
            while (g_bar_gen == gen){ __nanosleep(64); }
        }
    }
    __syncthreads();
    __threadfence();
}

__global__ void __launch_bounds__(NTHR, 1)
fused_loss(const float* __restrict__ outputs,
           const float* __restrict__ labels,
           const float* __restrict__ xs,
           const float* __restrict__ ys,
           const float* __restrict__ st,
           float* __restrict__ out){
    __shared__ float4 s4a[NG];      // phase A: GT box;  phase C: GT box
    __shared__ float2 s2a[NG];      // GT center
    __shared__ float  s1a[NG];      // phase C: GT area
    __shared__ int    scv;
    __shared__ float  rmn[8], rmx[8], rrm[8];
    __shared__ float  bymin, bymax, brmax;
    __shared__ int    wcnt[8], wbase[8], blkbase;
    __shared__ float  ssum[NTHR];
    __shared__ int    scnt2[NTHR];

    int tid  = threadIdx.x;
    int wid  = tid >> 5;
    int lane = tid & 31;
    const unsigned FULL = 0xffffffffu;

    // ===================== Phase A: fg mask + compaction =====================
    for (int tile = blockIdx.x; tile < NTILE; tile += NBLK){
        int b  = tile / 33;
        int a  = (tile % 33)*NTHR + tid;
        bool valid = (a < NA);
        float xc=0.f, yc=0.f, r=0.f;
        if (valid){
            float s  = st[a];
            xc = (xs[a] + 0.5f) * s;
            yc = (ys[a] + 0.5f) * s;
            r  = 2.5f * s;
        }

        {   // block reduce ymin/ymax/rmax
            float mn = valid ? yc :  1e30f;
            float mx = valid ? yc : -1e30f;
            float rm = valid ? r  :  0.0f;
            #pragma unroll
            for (int off = 16; off; off >>= 1){
                mn = fminf(mn, __shfl_down_sync(FULL, mn, off));
                mx = fmaxf(mx, __shfl_down_sync(FULL, mx, off));
                rm = fmaxf(rm, __shfl_down_sync(FULL, rm, off));
            }
            if (lane == 0){ rmn[wid] = mn; rmx[wid] = mx; rrm[wid] = rm; }
        }
        if (tid == 0) scv = 0;
        __syncthreads();
        if (tid == 0){
            float mn = rmn[0], mx = rmx[0], rm = rrm[0];
            #pragma unroll
            for (int i = 1; i < 8; i++){
                mn = fminf(mn, rmn[i]); mx = fmaxf(mx, rmx[i]); rm = fmaxf(rm, rrm[i]);
            }
            bymin = mn; bymax = mx; brmax = rm;
        }
        __syncthreads();
        float ymin = bymin, ymax = bymax, rmaxb = brmax;

        if (tid < NG){
            const float* L = labels + (size_t)(b*NG + tid)*5;
            float l0=L[0], gcx=L[1], gcy=L[2], gw=L[3], gh=L[4];
            if ((l0+gcx+gcy+gw+gh) > 0.0f){
                float y0 = gcy - gh*0.5f, y1 = gcy + gh*0.5f;
                bool boxy = (ymax > y0) && (ymin < y1);
                bool ctry = (ymax > gcy - rmaxb) && (ymin < gcy + rmaxb);
                if (boxy || ctry){
                    int p = atomicAdd(&scv, 1);
                    s4a[p] = make_float4(gcx - gw*0.5f, y0, gcx + gw*0.5f, y1);
                    s2a[p] = make_float2(gcx, gcy);
                }
            }
        }
        __syncthreads();
        int cv = scv;

        bool fg = false;
        if (valid){
            for (int g = 0; g < cv; g++){
                float4 bx = s4a[g];
                float2 cn = s2a[g];
                bool ib = (xc > bx.x) && (xc < bx.z) && (yc > bx.y) && (yc < bx.w);
                bool ic = (fabsf(xc - cn.x) < r) && (fabsf(yc - cn.y) < r);
                if (ib || ic){ fg = true; break; }
            }
            g_cnt[b*NA + a] = 0;
        }

        unsigned ball = __ballot_sync(FULL, fg);
        if (lane == 0) wcnt[wid] = __popc(ball);
        __syncthreads();
        if (tid == 0){
            int tot = 0;
            #pragma unroll
            for (int i = 0; i < 8; i++){ wbase[i] = tot; tot += wcnt[i]; }
            blkbase = tot ? atomicAdd(&g_nfg[b], tot) : 0;
        }
        __syncthreads();

        if (fg){
            int idx = b*NA + a;
            const float* o = outputs + (size_t)idx*6;
            float2 c2 = *(const float2*)(o);
            float2 w2 = *(const float2*)(o + 2);
            float2 oc = *(const float2*)(o + 4);
            float sig_o = 1.0f/(1.0f + expf(-oc.x));
            float sig_c = 1.0f/(1.0f + expf(-oc.y));
            float clsc = -logf(sqrtf(sig_c * sig_o) + 1e-9f);
            int pos = b*NA + blkbase + wbase[wid] + __popc(ball & ((1u << lane) - 1u));
            g_cidx[pos] = a;
            g_cbox[pos] = make_float4(c2.x, c2.y, w2.x, w2.y);
            g_cgeo[pos] = make_float4(xc, yc, r, clsc);
        }
        __syncthreads();
    }

    gridbar();

    // ===================== Phase B: per-GT assignment =====================
    for (int w = blockIdx.x*8 + wid; w < NB*NG; w += NBLK*8){
        int b = w / NG, g = w % NG;
        const float* L = labels + (size_t)(b*NG + g)*5;
        float l0=L[0], gcx=L[1], gcy=L[2], gw=L[3], gh=L[4];
        if (!((l0+gcx+gcy+gw+gh) > 0.0f)) continue;

        float gl = gcx - gw*0.5f, gr_ = gcx + gw*0.5f;
        float gt_ = gcy - gh*0.5f, gb = gcy + gh*0.5f;
        float garea = gw*gh;

        int nfg = g_nfg[b];
        const int*    cidx = g_cidx + b*NA;
        const float4* cbox = g_cbox + b*NA;
        const float4* cgeo = g_cgeo + b*NA;

        float tc[10]; int ti[10]; float tv[10]; float tu[10];
        #pragma unroll
        for (int k=0;k<10;k++){ tc[k]=3e38f; ti[k]=0x7fffffff; tv[k]=0.0f; tu[k]=0.0f; }

        for (int j = lane; j < nfg; j += 32){
            float4 bb = cbox[j];
            float4 ge = cgeo[j];
            int    a  = cidx[j];
            float tlx = fmaxf(gl,  bb.x - bb.z*0.5f);
            float tly = fmaxf(gt_, bb.y - bb.w*0.5f);
            float brx = fminf(gr_, bb.x + bb.z*0.5f);
            float bry = fminf(gb,  bb.y + bb.w*0.5f);
            float iw = fmaxf(brx - tlx, 0.0f);
            float ih = fmaxf(bry - tly, 0.0f);
            float inter = iw*ih;
            float iou = inter / (garea + bb.z*bb.w - inter + 1e-12f);
            bool ib = (ge.x > gl) && (ge.x < gr_) && (ge.y > gt_) && (ge.y < gb);
            bool ic = (fabsf(ge.x - gcx) < ge.z) && (fabsf(ge.y - gcy) < ge.z);
            bool geo = ib && ic;
            float cost = ge.w - 3.0f*logf(iou + 1e-8f) + (geo ? 0.0f : 100000.0f);

            if (iou > tu[9]){
                float v = iou;
                #pragma unroll
                for (int k=0;k<10;k++){
                    if (v > tu[k]){ float t = tu[k]; tu[k] = v; v = t; }
                }
            }
            if (cost < tc[9] || (cost == tc[9] && a < ti[9])){
                float cc = cost; int ii = a; float vv = iou;
                #pragma unroll
                for (int k=0;k<10;k++){
                    bool lt = (cc < tc[k]) || (cc == tc[k] && ii < ti[k]);
                    if (lt){
                        float t0=tc[k]; tc[k]=cc; cc=t0;
                        int   t1=ti[k]; ti[k]=ii; ii=t1;
                        float t2=tv[k]; tv[k]=vv; vv=t2;
                    }
                }
            }
        }

        float su = 0.0f;
        #pragma unroll
        for (int r = 0; r < 10; r++){
            float bv = tu[0];
            int   bl = lane;
            #pragma unroll
            for (int off = 16; off; off >>= 1){
                float ov = __shfl_down_sync(FULL, bv, off);
                int   ol = __shfl_down_sync(FULL, bl, off);
                if (ov > bv){ bv = ov; bl = ol; }
            }
            bv = __shfl_sync(FULL, bv, 0);
            bl = __shfl_sync(FULL, bl, 0);
            if (lane == bl){
                #pragma unroll
                for (int k=0;k<9;k++) tu[k] = tu[k+1];
                tu[9] = 0.0f;
            }
            su += bv;
        }
        int dynk = (int)su;
        if (dynk < 1) dynk = 1;

        for (int r = 0; r < dynk; r++){
            float bc  = tc[0];
            int   bi  = ti[0];
            float bvv = tv[0];
            int   bl  = lane;
            #pragma unroll
            for (int off = 16; off; off >>= 1){
                float oc = __shfl_down_sync(FULL, bc,  off);
                int   oi = __shfl_down_sync(FULL, bi,  off);
                float ov = __shfl_down_sync(FULL, bvv, off);
                int   ol = __shfl_down_sync(FULL, bl,  off);
                if (oc < bc || (oc == bc && oi < bi)){ bc=oc; bi=oi; bvv=ov; bl=ol; }
            }
            bc  = __shfl_sync(FULL, bc,  0);
            bi  = __shfl_sync(FULL, bi,  0);
            bvv = __shfl_sync(FULL, bvv, 0);
            bl  = __shfl_sync(FULL, bl,  0);
            if (bc >= 1e9f) break;
            if (lane == bl){
                #pragma unroll
                for (int k=0;k<9;k++){ tc[k]=tc[k+1]; ti[k]=ti[k+1]; tv[k]=tv[k+1]; }
                tc[9] = 3e38f; ti[9] = 0x7fffffff; tv[9] = 0.0f;
            }
            if (lane == 0){
                atomicAdd(&g_cnt[b*NA + bi], 1);
                g_miou[b*NA + bi] = bvv;     // raced only when cnt>1 (then unused)
            }
        }
    }

    gridbar();

    // ===================== Phase C: loss over compacted fg =====================
    float accS = 0.0f; int accN = 0;
    for (int tile = blockIdx.x; tile < NTILE; tile += NBLK){
        int b = tile / 33;
        int j = (tile % 33)*NTHR + tid;

        if (tid == 0) scv = 0;
        __syncthreads();
        if (tid < NG){
            const float* L = labels + (size_t)(b*NG + tid)*5;
            float l0=L[0], gcx=L[1], gcy=L[2], gw=L[3], gh=L[4];
            if ((l0+gcx+gcy+gw+gh) > 0.0f){
                int p = atomicAdd(&scv, 1);
                s4a[p] = make_float4(gcx - gw*0.5f, gcy - gh*0.5f,
                                     gcx + gw*0.5f, gcy + gh*0.5f);
                s2a[p] = make_float2(gcx, gcy);
                s1a[p] = gw*gh;
            }
        }
        __syncthreads();
        int nv = scv;

        int nfg = g_nfg[b];
        if (j < nfg){
            int a   = g_cidx[b*NA + j];
            int cnt = g_cnt[b*NA + a];
            if (cnt >= 1){
                accN++;
                float pred_iou;
                if (cnt == 1){
                    pred_iou = g_miou[b*NA + a];
                } else {
                    float4 bb = g_cbox[b*NA + j];
                    float4 ge = g_cgeo[b*NA + j];
                    float barea = bb.z*bb.w;
                    float bestc = 3e38f, besti = 0.0f;
                    for (int g = 0; g < nv; g++){
                        float4 bx = s4a[g];
                        float2 cn = s2a[g];
                        float tlx = fmaxf(bx.x, bb.x - bb.z*0.5f);
                        float tly = fmaxf(bx.y, bb.y - bb.w*0.5f);
                        float brx = fminf(bx.z, bb.x + bb.z*0.5f);
                        float bry = fminf(bx.w, bb.y + bb.w*0.5f);
                        float iw = fmaxf(brx - tlx, 0.0f);
                        float ih = fmaxf(bry - tly, 0.0f);
                        float inter = iw*ih;
                        float iou = inter / (s1a[g] + barea - inter + 1e-12f);
                        bool ib = (ge.x > bx.x) && (ge.x < bx.z) &&
                                  (ge.y > bx.y) && (ge.y < bx.w);
                        bool ic = (fabsf(ge.x - cn.x) < ge.z) && (fabsf(ge.y - cn.y) < ge.z);
                        bool geo = ib && ic;
                        float cost = ge.w - 3.0f*logf(iou + 1e-8f) + (geo ? 0.0f : 100000.0f);
                        if (cost < bestc){ bestc = cost; besti = iou; }
                    }
                    pred_iou = besti;
                }
                float x = outputs[(size_t)(b*NA + a)*6 + 5];
                float sp_p = softplus(x);
                float sp_n = softplus(-x);
                accS += pred_iou*sp_n + (1.0f - pred_iou)*sp_p;
            }
        }
        __syncthreads();
    }

    // block reduce partials (fixed order)
    ssum[tid] = accS;
    scnt2[tid] = accN;
    __syncthreads();
    for (int o = 128; o; o >>= 1){
        if (tid < o){ ssum[tid] += ssum[tid+o]; scnt2[tid] += scnt2[tid+o]; }
        __syncthreads();
    }
    if (tid == 0){ g_psum[blockIdx.x] = ssum[0]; g_pcnt[blockIdx.x] = scnt2[0]; }

    gridbar();

    // ===================== block 0: final reduce + state reset =====================
    if (blockIdx.x == 0){
        float s = 0.0f; int c = 0;
        if (tid < NBLK){ s = g_psum[tid]; c = g_pcnt[tid]; }
        ssum[tid] = s; scnt2[tid] = c;
        __syncthreads();
        for (int o = 128; o; o >>= 1){
            if (tid < o){ ssum[tid] += ssum[tid+o]; scnt2[tid] += scnt2[tid+o]; }
            __syncthreads();
        }
        if (tid == 0){
            float nf = (float)scnt2[0];
            if (nf < 1.0f) nf = 1.0f;
            out[0] = ssum[0] / nf;
        }
        if (tid < NB) g_nfg[tid] = 0;   // reset for next graph replay
    }
}

extern "C" void kernel_launch(void* const* d_in, const int* in_sizes, int n_in,
                              void* d_out, int out_size){
    const float* outputs = (const float*)d_in[0];  // [32, 8400, 6]
    const float* labels  = (const float*)d_in[1];  // [32, 100, 5]
    const float* xs      = (const float*)d_in[2];  // [1, 8400]
    const float* ys      = (const float*)d_in[3];  // [1, 8400]
    const float* st      = (const float*)d_in[4];  // [1, 8400]

    fused_loss<<<NBLK, NTHR>>>(outputs, labels, xs, ys, st, (float*)d_out);
}

// round 9
// speedup vs baseline: 3.0406x; 3.0406x over previous
#include <cuda_runtime.h>
#include <math.h>

#define NB 32
#define NA 8400
#define NG 100
#define BA (NB*NA)
#define NBLK3 (33*32)

// ---- device scratch (static globals; zero-initialized at load) ----
__device__ int    g_cnt[BA];
__device__ float  g_miou[BA];
__device__ int    g_nfg[NB];        // reset by k3 last block
__device__ int    g_cidx[BA];
__device__ float4 g_cbox[BA];       // compacted pred bbox CORNERS x0,y0,x1,y1
__device__ float4 g_cgeo[BA];       // xc, yc, r, clsc
__device__ float  g_psum[NBLK3];
__device__ int    g_pcnt[NBLK3];
__device__ int    g_done;

#define LN2X3 2.0794415416798357f   // 3*ln(2)

__device__ __forceinline__ float softplus(float x){
    return fmaxf(x, 0.0f) + log1pf(expf(-fabsf(x)));
}

// ---------------------------------------------------------------------------
// Kernel 1: fg mask + compaction, per-block GT y-culling. Corners stored.
// ---------------------------------------------------------------------------
__global__ void k1_fg_compact(const float* __restrict__ outputs,
                              const float* __restrict__ labels,
                              const float* __restrict__ xs,
                              const float* __restrict__ ys,
                              const float* __restrict__ st){
    __shared__ float4 cgt[NG];
    __shared__ float2 ccen[NG];
    __shared__ int    scv;
    __shared__ float  rmn[8], rmx[8], rrm[8];
    __shared__ float  bymin, bymax, brmax;
    __shared__ int    wcnt[8], wbase[8], blkbase;

    int b = blockIdx.y;
    int a = blockIdx.x*blockDim.x + threadIdx.x;
    bool valid = (a < NA);
    float xc=0.f, yc=0.f, r=0.f;
    if (valid){
        float s  = st[a];
        xc = (xs[a] + 0.5f) * s;
        yc = (ys[a] + 0.5f) * s;
        r  = 2.5f * s;
    }

    int wid = threadIdx.x >> 5, lane = threadIdx.x & 31;
    {
        float mn = valid ? yc :  1e30f;
        float mx = valid ? yc : -1e30f;
        float rm = valid ? r  :  0.0f;
        #pragma unroll
        for (int off = 16; off; off >>= 1){
            mn = fminf(mn, __shfl_down_sync(0xffffffffu, mn, off));
            mx = fmaxf(mx, __shfl_down_sync(0xffffffffu, mx, off));
            rm = fmaxf(rm, __shfl_down_sync(0xffffffffu, rm, off));
        }
        if (lane == 0){ rmn[wid] = mn; rmx[wid] = mx; rrm[wid] = rm; }
    }
    if (threadIdx.x == 0) scv = 0;
    __syncthreads();
    if (threadIdx.x == 0){
        float mn = rmn[0], mx = rmx[0], rm = rrm[0];
        #pragma unroll
        for (int i = 1; i < 8; i++){
            mn = fminf(mn, rmn[i]); mx = fmaxf(mx, rmx[i]); rm = fmaxf(rm, rrm[i]);
        }
        bymin = mn; bymax = mx; brmax = rm;
    }
    __syncthreads();
    float ymin = bymin, ymax = bymax, rmaxb = brmax;

    if (threadIdx.x < NG){
        const float* L = labels + (size_t)(b*NG + threadIdx.x)*5;
        float l0=L[0], gcx=L[1], gcy=L[2], gw=L[3], gh=L[4];
        if ((l0+gcx+gcy+gw+gh) > 0.0f){
            float y0 = gcy - gh*0.5f, y1 = gcy + gh*0.5f;
            bool boxy = (ymax > y0) && (ymin < y1);
            bool ctry = (ymax > gcy - rmaxb) && (ymin < gcy + rmaxb);
            if (boxy || ctry){
                int p = atomicAdd(&scv, 1);
                cgt[p]  = make_float4(gcx - gw*0.5f, y0, gcx + gw*0.5f, y1);
                ccen[p] = make_float2(gcx, gcy);
            }
        }
    }
    __syncthreads();
    int cv = scv;

    bool fg = false;
    if (valid){
        for (int g = 0; g < cv; g++){
            float4 bx = cgt[g];
            float2 cn = ccen[g];
            bool ib = (xc > bx.x) && (xc < bx.z) && (yc > bx.y) && (yc < bx.w);
            bool ic = (fabsf(xc - cn.x) < r) && (fabsf(yc - cn.y) < r);
            if (ib || ic){ fg = true; break; }
        }
        g_cnt[b*NA + a] = 0;
    }

    unsigned ball = __ballot_sync(0xffffffffu, fg);
    if (lane == 0) wcnt[wid] = __popc(ball);
    __syncthreads();
    if (threadIdx.x == 0){
        int tot = 0;
        #pragma unroll
        for (int i = 0; i < 8; i++){ wbase[i] = tot; tot += wcnt[i]; }
        blkbase = tot ? atomicAdd(&g_nfg[b], tot) : 0;
    }
    __syncthreads();

    if (fg){
        int idx = b*NA + a;
        const float* o = outputs + (size_t)idx*6;
        float2 c2 = *(const float2*)(o);
        float2 w2 = *(const float2*)(o + 2);
        float2 oc = *(const float2*)(o + 4);
        float sig_o = __fdividef(1.0f, 1.0f + __expf(-oc.x));
        float sig_c = __fdividef(1.0f, 1.0f + __expf(-oc.y));
        float clsc = -__logf(sqrtf(sig_c * sig_o) + 1e-9f);
        int pos = b*NA + blkbase + wbase[wid] + __popc(ball & ((1u << lane) - 1u));
        g_cidx[pos] = a;
        g_cbox[pos] = make_float4(c2.x - w2.x*0.5f, c2.y - w2.y*0.5f,
                                  c2.x + w2.x*0.5f, c2.y + w2.y*0.5f);
        g_cgeo[pos] = make_float4(xc, yc, r, clsc);
    }
}

// ---------------------------------------------------------------------------
// Kernel 2: 1 warp/GT; UNIFORM trip count so warp intrinsics are legal;
// warp-global admission thresholds keep insertion chains rare.
// ---------------------------------------------------------------------------
__global__ void k2_assign(const float* __restrict__ outputs,
                          const float* __restrict__ labels){
    int b    = blockIdx.y;
    int wid  = threadIdx.x >> 5;
    int lane = threadIdx.x & 31;
    int g    = blockIdx.x*8 + wid;
    if (g >= NG) return;

    const float* L = labels + (size_t)(b*NG + g)*5;
    float l0=L[0], gcx=L[1], gcy=L[2], gw=L[3], gh=L[4];
    if (!((l0+gcx+gcy+gw+gh) > 0.0f)) return;

    float gl = gcx - gw*0.5f, gr_ = gcx + gw*0.5f;
    float gt_ = gcy - gh*0.5f, gb = gcy + gh*0.5f;
    float garea = gw*gh;

    int nfg = g_nfg[b];
    const int*    cidx = g_cidx + b*NA;
    const float4* cbox = g_cbox + b*NA;
    const float4* cgeo = g_cgeo + b*NA;
    const unsigned FULL = 0xffffffffu;

    float tc[10]; int ti[10]; float tu[10];
    #pragma unroll
    for (int k=0;k<10;k++){ tc[k]=3e38f; ti[k]=0x7fffffff; tu[k]=0.0f; }
    float thrI = 0.0f, thrC = 3e38f;   // warp-global admission thresholds

    int niter = (nfg + 31) >> 5;       // uniform across the warp
    for (int it = 0; it < niter; it++){
        int j = it*32 + lane;
        bool act = (j < nfg);
        float iou = 0.0f, cost = 3e38f;
        int a = 0x7fffffff;
        if (act){
            float4 bb = cbox[j];   // corners
            float4 ge = cgeo[j];
            a = cidx[j];
            float tlx = fmaxf(gl,  bb.x);
            float tly = fmaxf(gt_, bb.y);
            float brx = fminf(gr_, bb.z);
            float bry = fminf(gb,  bb.w);
            float iw = fmaxf(brx - tlx, 0.0f);
            float ih = fmaxf(bry - tly, 0.0f);
            float inter = iw*ih;
            float barea = (bb.z - bb.x)*(bb.w - bb.y);
            iou = __fdividef(inter, garea + barea - inter + 1e-12f);
            bool ib = (ge.x > gl) && (ge.x < gr_) && (ge.y > gt_) && (ge.y < gb);
            bool ic = (fabsf(ge.x - gcx) < ge.z) && (fabsf(ge.y - gcy) < ge.z);
            cost = ge.w - LN2X3*__log2f(iou + 1e-8f) + ((ib && ic) ? 0.0f : 100000.0f);
        }

        // admission: thr >= current global 10th (each lane's 10th bounds it)
        bool doI = act && (iou > 0.0f) && (iou >= thrI);
        bool doC = act && (cost <= thrC);
        if (__any_sync(FULL, doI || doC)){
            if (doI && iou > tu[9]){
                float v = iou;
                #pragma unroll
                for (int k=0;k<10;k++){
                    float nmx = fmaxf(tu[k], v);
                    v = fminf(tu[k], v);
                    tu[k] = nmx;
                }
            }
            if (doC && (cost < tc[9] || (cost == tc[9] && a < ti[9]))){
                float cc = cost; int ii = a;
                #pragma unroll
                for (int k=0;k<10;k++){
                    bool lt = (cc < tc[k]) || (cc == tc[k] && ii < ti[k]);
                    float nc = lt ? cc : tc[k];  int ni = lt ? ii : ti[k];
                    cc = lt ? tc[k] : cc;        ii = lt ? ti[k] : ii;
                    tc[k] = nc; ti[k] = ni;
                }
            }
            // refresh warp-global thresholds (all 32 lanes participate)
            float t9 = tu[9], c9 = tc[9];
            #pragma unroll
            for (int off = 16; off; off >>= 1){
                t9 = fminf(t9, __shfl_xor_sync(FULL, t9, off));
                c9 = fminf(c9, __shfl_xor_sync(FULL, c9, off));
            }
            thrI = t9; thrC = c9;
        }
    }

    // merge ious: 10 rounds warp argmax (descending-order sum)
    float su = 0.0f;
    #pragma unroll
    for (int r = 0; r < 10; r++){
        float bv = tu[0]; int bl = lane;
        #pragma unroll
        for (int off = 16; off; off >>= 1){
            float ov = __shfl_down_sync(FULL, bv, off);
            int   ol = __shfl_down_sync(FULL, bl, off);
            if (ov > bv){ bv = ov; bl = ol; }
        }
        bv = __shfl_sync(FULL, bv, 0);
        bl = __shfl_sync(FULL, bl, 0);
        if (lane == bl){
            #pragma unroll
            for (int k=0;k<9;k++) tu[k] = tu[k+1];
            tu[9] = 0.0f;
        }
        su += bv;
    }
    int dynk = (int)su;
    if (dynk < 1) dynk = 1;

    // merge costs: dynk rounds warp lex-argmin; lane0 scatters + recomputes iou
    for (int r = 0; r < dynk; r++){
        float bc = tc[0]; int bi = ti[0]; int bl = lane;
        #pragma unroll
        for (int off = 16; off; off >>= 1){
            float oc = __shfl_down_sync(FULL, bc, off);
            int   oi = __shfl_down_sync(FULL, bi, off);
            int   ol = __shfl_down_sync(FULL, bl, off);
            if (oc < bc || (oc == bc && oi < bi)){ bc=oc; bi=oi; bl=ol; }
        }
        bc = __shfl_sync(FULL, bc, 0);
        bi = __shfl_sync(FULL, bi, 0);
        bl = __shfl_sync(FULL, bl, 0);
        if (bc >= 1e9f) break;
        if (lane == bl){
            #pragma unroll
            for (int k=0;k<9;k++){ tc[k]=tc[k+1]; ti[k]=ti[k+1]; }
            tc[9] = 3e38f; ti[9] = 0x7fffffff;
        }
        if (lane == 0){
            atomicAdd(&g_cnt[b*NA + bi], 1);
            const float* o = outputs + (size_t)(b*NA + bi)*6;
            float bcx=o[0], bcy=o[1], bw2=o[2]*0.5f, bh2=o[3]*0.5f;
            float tlx = fmaxf(gl,  bcx-bw2), tly = fmaxf(gt_, bcy-bh2);
            float brx = fminf(gr_, bcx+bw2), bry = fminf(gb,  bcy+bh2);
            float iw = fmaxf(brx-tlx, 0.f), ih = fmaxf(bry-tly, 0.f);
            float inter = iw*ih;
            float iou = __fdividef(inter, garea + 4.f*bw2*bh2 - inter + 1e-12f);
            g_miou[b*NA + bi] = iou;   // raced only when cnt>1 (then unused)
        }
    }
}

// ---------------------------------------------------------------------------
// Kernel 3: loss over compacted fg + fused last-block final reduce.
// ---------------------------------------------------------------------------
__global__ void k3_loss(const float* __restrict__ outputs,
                        const float* __restrict__ labels,
                        float* __restrict__ out){
    __shared__ float4 sgt[NG];
    __shared__ float2 scen[NG];
    __shared__ float  sarea[NG];
    __shared__ int    snv;
    __shared__ float  ssum[256];
    __shared__ int    scnt[256];
    __shared__ bool   isLast;

    int b = blockIdx.y;
    if (threadIdx.x == 0) snv = 0;
    __syncthreads();
    if (threadIdx.x < NG){
        const float* L = labels + (size_t)(b*NG + threadIdx.x)*5;
        float l0=L[0], gcx=L[1], gcy=L[2], gw=L[3], gh=L[4];
        if ((l0+gcx+gcy+gw+gh) > 0.0f){
            int p = atomicAdd(&snv, 1);
            sgt[p]   = make_float4(gcx - gw*0.5f, gcy - gh*0.5f,
                                   gcx + gw*0.5f, gcy + gh*0.5f);
            scen[p]  = make_float2(gcx, gcy);
            sarea[p] = gw*gh;
        }
    }
    __syncthreads();
    int nv = snv;

    int nfg = g_nfg[b];
    int j = blockIdx.x*blockDim.x + threadIdx.x;
    float term = 0.0f;
    int   isfg = 0;
    if (j < nfg){
        int a   = g_cidx[b*NA + j];
        int cnt = g_cnt[b*NA + a];
        if (cnt >= 1){
            isfg = 1;
            float pred_iou;
            if (cnt == 1){
                pred_iou = g_miou[b*NA + a];
            } else {
                float4 bb = g_cbox[b*NA + j];   // corners
                float4 ge = g_cgeo[b*NA + j];
                float barea = (bb.z - bb.x)*(bb.w - bb.y);
                float bestc = 3e38f, besti = 0.0f;
                for (int g = 0; g < nv; g++){
                    float4 bx = sgt[g];
                    float2 cn = scen[g];
                    float tlx = fmaxf(bx.x, bb.x);
                    float tly = fmaxf(bx.y, bb.y);
                    float brx = fminf(bx.z, bb.z);
                    float bry = fminf(bx.w, bb.w);
                    float iw = fmaxf(brx - tlx, 0.0f);
                    float ih = fmaxf(bry - tly, 0.0f);
                    float inter = iw*ih;
                    float iou = __fdividef(inter, sarea[g] + barea - inter + 1e-12f);
                    bool ib = (ge.x > bx.x) && (ge.x < bx.z) &&
                              (ge.y > bx.y) && (ge.y < bx.w);
                    bool ic = (fabsf(ge.x - cn.x) < ge.z) && (fabsf(ge.y - cn.y) < ge.z);
                    float cost = ge.w - LN2X3*__log2f(iou + 1e-8f) +
                                 ((ib && ic) ? 0.0f : 100000.0f);
                    if (cost < bestc){ bestc = cost; besti = iou; }
                }
                pred_iou = besti;
            }
            float x = outputs[(size_t)(b*NA + a)*6 + 5];
            float sp_p = softplus(x);
            float sp_n = softplus(-x);
            term = pred_iou*sp_n + (1.0f - pred_iou)*sp_p;
        }
    }
    ssum[threadIdx.x] = term;
    scnt[threadIdx.x] = isfg;
    __syncthreads();
    for (int o = 128; o; o >>= 1){
        if (threadIdx.x < o){
            ssum[threadIdx.x] += ssum[threadIdx.x + o];
            scnt[threadIdx.x] += scnt[threadIdx.x + o];
        }
        __syncthreads();
    }
    if (threadIdx.x == 0){
        int blk = blockIdx.y*gridDim.x + blockIdx.x;
        g_psum[blk] = ssum[0];
        g_pcnt[blk] = scnt[0];
        __threadfence();
        int t = atomicAdd(&g_done, 1);
        isLast = (t == NBLK3 - 1);
    }
    __syncthreads();

    if (isLast){
        float s = 0.0f; int c = 0;
        for (int i = threadIdx.x; i < NBLK3; i += 256){ s += g_psum[i]; c += g_pcnt[i]; }
        ssum[threadIdx.x] = s; scnt[threadIdx.x] = c;
        __syncthreads();
        for (int o = 128; o; o >>= 1){
            if (threadIdx.x < o){
                ssum[threadIdx.x] += ssum[threadIdx.x+o];
                scnt[threadIdx.x] += scnt[threadIdx.x+o];
            }
            __syncthreads();
        }
        if (threadIdx.x == 0){
            float nf = (float)scnt[0];
            if (nf < 1.0f) nf = 1.0f;
            out[0] = ssum[0] / nf;
            g_done = 0;
        }
        if (threadIdx.x < NB) g_nfg[threadIdx.x] = 0;
    }
}

extern "C" void kernel_launch(void* const* d_in, const int* in_sizes, int n_in,
                              void* d_out, int out_size){
    const float* outputs = (const float*)d_in[0];  // [32, 8400, 6]
    const float* labels  = (const float*)d_in[1];  // [32, 100, 5]
    const float* xs      = (const float*)d_in[2];  // [1, 8400]
    const float* ys      = (const float*)d_in[3];  // [1, 8400]
    const float* st      = (const float*)d_in[4];  // [1, 8400]

    dim3 ganchor(33, NB);
    k1_fg_compact<<<ganchor, 256>>>(outputs, labels, xs, ys, st);
    k2_assign<<<dim3(13, NB), 256>>>(outputs, labels);
    k3_loss<<<ganchor, 256>>>(outputs, labels, (float*)d_out);
}

// round 10
// speedup vs baseline: 3.4838x; 1.1458x over previous
#include <cuda_runtime.h>
#include <math.h>

#define NB 32
#define NA 8400
#define NG 100
#define BA (NB*NA)
#define NBLK3 (33*32)

// ---- device scratch (static globals; zero-initialized at load) ----
__device__ int    g_cnt[BA];
__device__ float  g_miou[BA];
__device__ int    g_nfg[NB];        // reset by k3 last block
__device__ int    g_cidx[BA];
__device__ float4 g_cbox[BA];       // compacted pred bbox CORNERS x0,y0,x1,y1
__device__ float4 g_cgeo[BA];       // xc, yc, r, clsc
__device__ float  g_psum[NBLK3];
__device__ int    g_pcnt[NBLK3];
__device__ int    g_done;

#define LN2X3 2.0794415416798357f   // 3*ln(2)

__device__ __forceinline__ float softplus(float x){
    return fmaxf(x, 0.0f) + log1pf(expf(-fabsf(x)));
}

// ---------------------------------------------------------------------------
// Kernel 1: fg mask + compaction, per-block GT y-culling. Corners stored.
// ---------------------------------------------------------------------------
__global__ void k1_fg_compact(const float* __restrict__ outputs,
                              const float* __restrict__ labels,
                              const float* __restrict__ xs,
                              const float* __restrict__ ys,
                              const float* __restrict__ st){
    __shared__ float4 cgt[NG];
    __shared__ float2 ccen[NG];
    __shared__ int    scv;
    __shared__ float  rmn[8], rmx[8], rrm[8];
    __shared__ float  bymin, bymax, brmax;
    __shared__ int    wcnt[8], wbase[8], blkbase;

    int b = blockIdx.y;
    int a = blockIdx.x*blockDim.x + threadIdx.x;
    bool valid = (a < NA);
    float xc=0.f, yc=0.f, r=0.f;
    if (valid){
        float s  = st[a];
        xc = (xs[a] + 0.5f) * s;
        yc = (ys[a] + 0.5f) * s;
        r  = 2.5f * s;
    }

    int wid = threadIdx.x >> 5, lane = threadIdx.x & 31;
    {
        float mn = valid ? yc :  1e30f;
        float mx = valid ? yc : -1e30f;
        float rm = valid ? r  :  0.0f;
        #pragma unroll
        for (int off = 16; off; off >>= 1){
            mn = fminf(mn, __shfl_down_sync(0xffffffffu, mn, off));
            mx = fmaxf(mx, __shfl_down_sync(0xffffffffu, mx, off));
            rm = fmaxf(rm, __shfl_down_sync(0xffffffffu, rm, off));
        }
        if (lane == 0){ rmn[wid] = mn; rmx[wid] = mx; rrm[wid] = rm; }
    }
    if (threadIdx.x == 0) scv = 0;
    __syncthreads();
    if (threadIdx.x == 0){
        float mn = rmn[0], mx = rmx[0], rm = rrm[0];
        #pragma unroll
        for (int i = 1; i < 8; i++){
            mn = fminf(mn, rmn[i]); mx = fmaxf(mx, rmx[i]); rm = fmaxf(rm, rrm[i]);
        }
        bymin = mn; bymax = mx; brmax = rm;
    }
    __syncthreads();
    float ymin = bymin, ymax = bymax, rmaxb = brmax;

    if (threadIdx.x < NG){
        const float* L = labels + (size_t)(b*NG + threadIdx.x)*5;
        float l0=L[0], gcx=L[1], gcy=L[2], gw=L[3], gh=L[4];
        if ((l0+gcx+gcy+gw+gh) > 0.0f){
            float y0 = gcy - gh*0.5f, y1 = gcy + gh*0.5f;
            bool boxy = (ymax > y0) && (ymin < y1);
            bool ctry = (ymax > gcy - rmaxb) && (ymin < gcy + rmaxb);
            if (boxy || ctry){
                int p = atomicAdd(&scv, 1);
                cgt[p]  = make_float4(gcx - gw*0.5f, y0, gcx + gw*0.5f, y1);
                ccen[p] = make_float2(gcx, gcy);
            }
        }
    }
    __syncthreads();
    int cv = scv;

    bool fg = false;
    if (valid){
        for (int g = 0; g < cv; g++){
            float4 bx = cgt[g];
            float2 cn = ccen[g];
            bool ib = (xc > bx.x) && (xc < bx.z) && (yc > bx.y) && (yc < bx.w);
            bool ic = (fabsf(xc - cn.x) < r) && (fabsf(yc - cn.y) < r);
            if (ib || ic){ fg = true; break; }
        }
        g_cnt[b*NA + a] = 0;
    }

    unsigned ball = __ballot_sync(0xffffffffu, fg);
    if (lane == 0) wcnt[wid] = __popc(ball);
    __syncthreads();
    if (threadIdx.x == 0){
        int tot = 0;
        #pragma unroll
        for (int i = 0; i < 8; i++){ wbase[i] = tot; tot += wcnt[i]; }
        blkbase = tot ? atomicAdd(&g_nfg[b], tot) : 0;
    }
    __syncthreads();

    if (fg){
        int idx = b*NA + a;
        const float* o = outputs + (size_t)idx*6;
        float2 c2 = *(const float2*)(o);
        float2 w2 = *(const float2*)(o + 2);
        float2 oc = *(const float2*)(o + 4);
        float sig_o = __fdividef(1.0f, 1.0f + __expf(-oc.x));
        float sig_c = __fdividef(1.0f, 1.0f + __expf(-oc.y));
        float clsc = -__logf(sqrtf(sig_c * sig_o) + 1e-9f);
        int pos = b*NA + blkbase + wbase[wid] + __popc(ball & ((1u << lane) - 1u));
        g_cidx[pos] = a;
        g_cbox[pos] = make_float4(c2.x - w2.x*0.5f, c2.y - w2.y*0.5f,
                                  c2.x + w2.x*0.5f, c2.y + w2.y*0.5f);
        g_cgeo[pos] = make_float4(xc, yc, r, clsc);
    }
}

// ---------------------------------------------------------------------------
// Kernel 2: 1 warp/GT; 4-way batched loads (MLP=4) ahead of the warp-sync
// admission block; warp-uniform trip count; admission thresholds.
// ---------------------------------------------------------------------------
__global__ void k2_assign(const float* __restrict__ outputs,
                          const float* __restrict__ labels){
    int b    = blockIdx.y;
    int wid  = threadIdx.x >> 5;
    int lane = threadIdx.x & 31;
    int g    = blockIdx.x*8 + wid;
    if (g >= NG) return;

    const float* L = labels + (size_t)(b*NG + g)*5;
    float l0=L[0], gcx=L[1], gcy=L[2], gw=L[3], gh=L[4];
    if (!((l0+gcx+gcy+gw+gh) > 0.0f)) return;

    float gl = gcx - gw*0.5f, gr_ = gcx + gw*0.5f;
    float gt_ = gcy - gh*0.5f, gb = gcy + gh*0.5f;
    float garea = gw*gh;

    int nfg = g_nfg[b];
    const int*    cidx = g_cidx + b*NA;
    const float4* cbox = g_cbox + b*NA;
    const float4* cgeo = g_cgeo + b*NA;
    const unsigned FULL = 0xffffffffu;

    float tc[10]; int ti[10]; float tu[10];
    #pragma unroll
    for (int k=0;k<10;k++){ tc[k]=3e38f; ti[k]=0x7fffffff; tu[k]=0.0f; }
    float thrI = 0.0f, thrC = 3e38f;

    int nblk = (nfg + 127) >> 7;      // blocks of 128 = 4 x 32, warp-uniform
    for (int ibk = 0; ibk < nblk; ibk++){
        int base = ibk*128 + lane;

        // ---- batched loads: all issued before any compute/sync (MLP=4) ----
        float4 bbv[4], gev[4]; int av[4]; bool actv[4];
        #pragma unroll
        for (int u = 0; u < 4; u++){
            int j = base + u*32;
            actv[u] = (j < nfg);
            if (actv[u]){
                bbv[u] = cbox[j];
                gev[u] = cgeo[j];
                av[u]  = cidx[j];
            } else {
                av[u] = 0x7fffffff;
            }
        }

        // ---- compute + admission per slot ----
        #pragma unroll
        for (int u = 0; u < 4; u++){
            bool act = actv[u];
            float iou = 0.0f, cost = 3e38f;
            int a = av[u];
            if (act){
                float4 bb = bbv[u];
                float4 ge = gev[u];
                float tlx = fmaxf(gl,  bb.x);
                float tly = fmaxf(gt_, bb.y);
                float brx = fminf(gr_, bb.z);
                float bry = fminf(gb,  bb.w);
                float iw = fmaxf(brx - tlx, 0.0f);
                float ih = fmaxf(bry - tly, 0.0f);
                float inter = iw*ih;
                float barea = (bb.z - bb.x)*(bb.w - bb.y);
                iou = __fdividef(inter, garea + barea - inter + 1e-12f);
                bool ib = (ge.x > gl) && (ge.x < gr_) && (ge.y > gt_) && (ge.y < gb);
                bool ic = (fabsf(ge.x - gcx) < ge.z) && (fabsf(ge.y - gcy) < ge.z);
                cost = ge.w - LN2X3*__log2f(iou + 1e-8f) + ((ib && ic) ? 0.0f : 100000.0f);
            }

            bool doI = act && (iou > 0.0f) && (iou >= thrI);
            bool doC = act && (cost <= thrC);
            if (__any_sync(FULL, doI || doC)){
                if (doI && iou > tu[9]){
                    float v = iou;
                    #pragma unroll
                    for (int k=0;k<10;k++){
                        float nmx = fmaxf(tu[k], v);
                        v = fminf(tu[k], v);
                        tu[k] = nmx;
                    }
                }
                if (doC && (cost < tc[9] || (cost == tc[9] && a < ti[9]))){
                    float cc = cost; int ii = a;
                    #pragma unroll
                    for (int k=0;k<10;k++){
                        bool lt = (cc < tc[k]) || (cc == tc[k] && ii < ti[k]);
                        float nc = lt ? cc : tc[k];  int ni = lt ? ii : ti[k];
                        cc = lt ? tc[k] : cc;        ii = lt ? ti[k] : ii;
                        tc[k] = nc; ti[k] = ni;
                    }
                }
                float t9 = tu[9], c9 = tc[9];
                #pragma unroll
                for (int off = 16; off; off >>= 1){
                    t9 = fminf(t9, __shfl_xor_sync(FULL, t9, off));
                    c9 = fminf(c9, __shfl_xor_sync(FULL, c9, off));
                }
                thrI = t9; thrC = c9;
            }
        }
    }

    // merge ious: 10 rounds warp argmax (descending-order sum)
    float su = 0.0f;
    #pragma unroll
    for (int r = 0; r < 10; r++){
        float bv = tu[0]; int bl = lane;
        #pragma unroll
        for (int off = 16; off; off >>= 1){
            float ov = __shfl_down_sync(FULL, bv, off);
            int   ol = __shfl_down_sync(FULL, bl, off);
            if (ov > bv){ bv = ov; bl = ol; }
        }
        bv = __shfl_sync(FULL, bv, 0);
        bl = __shfl_sync(FULL, bl, 0);
        if (lane == bl){
            #pragma unroll
            for (int k=0;k<9;k++) tu[k] = tu[k+1];
            tu[9] = 0.0f;
        }
        su += bv;
    }
    int dynk = (int)su;
    if (dynk < 1) dynk = 1;

    // merge costs: dynk rounds warp lex-argmin; lane0 scatters + recomputes iou
    for (int r = 0; r < dynk; r++){
        float bc = tc[0]; int bi = ti[0]; int bl = lane;
        #pragma unroll
        for (int off = 16; off; off >>= 1){
            float oc = __shfl_down_sync(FULL, bc, off);
            int   oi = __shfl_down_sync(FULL, bi, off);
            int   ol = __shfl_down_sync(FULL, bl, off);
            if (oc < bc || (oc == bc && oi < bi)){ bc=oc; bi=oi; bl=ol; }
        }
        bc = __shfl_sync(FULL, bc, 0);
        bi = __shfl_sync(FULL, bi, 0);
        bl = __shfl_sync(FULL, bl, 0);
        if (bc >= 1e9f) break;
        if (lane == bl){
            #pragma unroll
            for (int k=0;k<9;k++){ tc[k]=tc[k+1]; ti[k]=ti[k+1]; }
            tc[9] = 3e38f; ti[9] = 0x7fffffff;
        }
        if (lane == 0){
            atomicAdd(&g_cnt[b*NA + bi], 1);
            const float* o = outputs + (size_t)(b*NA + bi)*6;
            float bcx=o[0], bcy=o[1], bw2=o[2]*0.5f, bh2=o[3]*0.5f;
            float tlx = fmaxf(gl,  bcx-bw2), tly = fmaxf(gt_, bcy-bh2);
            float brx = fminf(gr_, bcx+bw2), bry = fminf(gb,  bcy+bh2);
            float iw = fmaxf(brx-tlx, 0.f), ih = fmaxf(bry-tly, 0.f);
            float inter = iw*ih;
            float iou = __fdividef(inter, garea + 4.f*bw2*bh2 - inter + 1e-12f);
            g_miou[b*NA + bi] = iou;   // raced only when cnt>1 (then unused)
        }
    }
}

// ---------------------------------------------------------------------------
// Kernel 3: loss over compacted fg + fused last-block final reduce.
// ---------------------------------------------------------------------------
__global__ void k3_loss(const float* __restrict__ outputs,
                        const float* __restrict__ labels,
                        float* __restrict__ out){
    __shared__ float4 sgt[NG];
    __shared__ float2 scen[NG];
    __shared__ float  sarea[NG];
    __shared__ int    snv;
    __shared__ float  ssum[256];
    __shared__ int    scnt[256];
    __shared__ bool   isLast;

    int b = blockIdx.y;
    if (threadIdx.x == 0) snv = 0;
    __syncthreads();
    if (threadIdx.x < NG){
        const float* L = labels + (size_t)(b*NG + threadIdx.x)*5;
        float l0=L[0], gcx=L[1], gcy=L[2], gw=L[3], gh=L[4];
        if ((l0+gcx+gcy+gw+gh) > 0.0f){
            int p = atomicAdd(&snv, 1);
            sgt[p]   = make_float4(gcx - gw*0.5f, gcy - gh*0.5f,
                                   gcx + gw*0.5f, gcy + gh*0.5f);
            scen[p]  = make_float2(gcx, gcy);
            sarea[p] = gw*gh;
        }
    }
    __syncthreads();
    int nv = snv;

    int nfg = g_nfg[b];
    int j = blockIdx.x*blockDim.x + threadIdx.x;
    float term = 0.0f;
    int   isfg = 0;
    if (j < nfg){
        int a   = g_cidx[b*NA + j];
        int cnt = g_cnt[b*NA + a];
        if (cnt >= 1){
            isfg = 1;
            float pred_iou;
            if (cnt == 1){
                pred_iou = g_miou[b*NA + a];
            } else {
                float4 bb = g_cbox[b*NA + j];   // corners
                float4 ge = g_cgeo[b*NA + j];
                float barea = (bb.z - bb.x)*(bb.w - bb.y);
                float bestc = 3e38f, besti = 0.0f;
                for (int g = 0; g < nv; g++){
                    float4 bx = sgt[g];
                    float2 cn = scen[g];
                    float tlx = fmaxf(bx.x, bb.x);
                    float tly = fmaxf(bx.y, bb.y);
                    float brx = fminf(bx.z, bb.z);
                    float bry = fminf(bx.w, bb.w);
                    float iw = fmaxf(brx - tlx, 0.0f);
                    float ih = fmaxf(bry - tly, 0.0f);
                    float inter = iw*ih;
                    float iou = __fdividef(inter, sarea[g] + barea - inter + 1e-12f);
                    bool ib = (ge.x > bx.x) && (ge.x < bx.z) &&
                              (ge.y > bx.y) && (ge.y < bx.w);
                    bool ic = (fabsf(ge.x - cn.x) < ge.z) && (fabsf(ge.y - cn.y) < ge.z);
                    float cost = ge.w - LN2X3*__log2f(iou + 1e-8f) +
                                 ((ib && ic) ? 0.0f : 100000.0f);
                    if (cost < bestc){ bestc = cost; besti = iou; }
                }
                pred_iou = besti;
            }
            float x = outputs[(size_t)(b*NA + a)*6 + 5];
            float sp_p = softplus(x);
            float sp_n = softplus(-x);
            term = pred_iou*sp_n + (1.0f - pred_iou)*sp_p;
        }
    }
    ssum[threadIdx.x] = term;
    scnt[threadIdx.x] = isfg;
    __syncthreads();
    for (int o = 128; o; o >>= 1){
        if (threadIdx.x < o){
            ssum[threadIdx.x] += ssum[threadIdx.x + o];
            scnt[threadIdx.x] += scnt[threadIdx.x + o];
        }
        __syncthreads();
    }
    if (threadIdx.x == 0){
        int blk = blockIdx.y*gridDim.x + blockIdx.x;
        g_psum[blk] = ssum[0];
        g_pcnt[blk] = scnt[0];
        __threadfence();
        int t = atomicAdd(&g_done, 1);
        isLast = (t == NBLK3 - 1);
    }
    __syncthreads();

    if (isLast){
        float s = 0.0f; int c = 0;
        for (int i = threadIdx.x; i < NBLK3; i += 256){ s += g_psum[i]; c += g_pcnt[i]; }
        ssum[threadIdx.x] = s; scnt[threadIdx.x] = c;
        __syncthreads();
        for (int o = 128; o; o >>= 1){
            if (threadIdx.x < o){
                ssum[threadIdx.x] += ssum[threadIdx.x+o];
                scnt[threadIdx.x] += scnt[threadIdx.x+o];
            }
            __syncthreads();
        }
        if (threadIdx.x == 0){
            float nf = (float)scnt[0];
            if (nf < 1.0f) nf = 1.0f;
            out[0] = ssum[0] / nf;
            g_done = 0;
        }
        if (threadIdx.x < NB) g_nfg[threadIdx.x] = 0;
    }
}

extern "C" void kernel_launch(void* const* d_in, const int* in_sizes, int n_in,
                              void* d_out, int out_size){
    const float* outputs = (const float*)d_in[0];  // [32, 8400, 6]
    const float* labels  = (const float*)d_in[1];  // [32, 100, 5]
    const float* xs      = (const float*)d_in[2];  // [1, 8400]
    const float* ys      = (const float*)d_in[3];  // [1, 8400]
    const float* st      = (const float*)d_in[4];  // [1, 8400]

    dim3 ganchor(33, NB);
    k1_fg_compact<<<ganchor, 256>>>(outputs, labels, xs, ys, st);
    k2_assign<<<dim3(13, NB), 256>>>(outputs, labels);
    k3_loss<<<ganchor, 256>>>(outputs, labels, (float*)d_out);
}

// round 11
// speedup vs baseline: 5.4175x; 1.5550x over previous
#include <cuda_runtime.h>
#include <math.h>

#define NB 32
#define NA 8400
#define NG 100
#define BA (NB*NA)
#define NBLK3 (33*32)

// ---- device scratch (static globals; zero-initialized at load) ----
__device__ int    g_cnt[BA];
__device__ float  g_miou[BA];
__device__ int    g_nfg[NB];        // reset by k3 last block
__device__ int    g_cidx[BA];
__device__ float4 g_cbox[BA];       // compacted pred bbox CORNERS x0,y0,x1,y1
__device__ float4 g_cgeo[BA];       // xc, yc, r, clsc
__device__ float  g_psum[NBLK3];
__device__ int    g_pcnt[NBLK3];
__device__ int    g_done;

#define LN2X3 2.0794415416798357f   // 3*ln(2)
#define FULLM 0xffffffffu

__device__ __forceinline__ float softplus(float x){
    return fmaxf(x, 0.0f) + log1pf(expf(-fabsf(x)));
}

// ---------------------------------------------------------------------------
// Kernel 1: fg mask + compaction, per-block GT y-culling. Corners stored.
// ---------------------------------------------------------------------------
__global__ void k1_fg_compact(const float* __restrict__ outputs,
                              const float* __restrict__ labels,
                              const float* __restrict__ xs,
                              const float* __restrict__ ys,
                              const float* __restrict__ st){
    __shared__ float4 cgt[NG];
    __shared__ float2 ccen[NG];
    __shared__ int    scv;
    __shared__ float  rmn[8], rmx[8], rrm[8];
    __shared__ float  bymin, bymax, brmax;
    __shared__ int    wcnt[8], wbase[8], blkbase;

    int b = blockIdx.y;
    int a = blockIdx.x*blockDim.x + threadIdx.x;
    bool valid = (a < NA);
    float xc=0.f, yc=0.f, r=0.f;
    if (valid){
        float s  = st[a];
        xc = (xs[a] + 0.5f) * s;
        yc = (ys[a] + 0.5f) * s;
        r  = 2.5f * s;
    }

    int wid = threadIdx.x >> 5, lane = threadIdx.x & 31;
    {
        float mn = valid ? yc :  1e30f;
        float mx = valid ? yc : -1e30f;
        float rm = valid ? r  :  0.0f;
        #pragma unroll
        for (int off = 16; off; off >>= 1){
            mn = fminf(mn, __shfl_down_sync(FULLM, mn, off));
            mx = fmaxf(mx, __shfl_down_sync(FULLM, mx, off));
            rm = fmaxf(rm, __shfl_down_sync(FULLM, rm, off));
        }
        if (lane == 0){ rmn[wid] = mn; rmx[wid] = mx; rrm[wid] = rm; }
    }
    if (threadIdx.x == 0) scv = 0;
    __syncthreads();
    if (threadIdx.x == 0){
        float mn = rmn[0], mx = rmx[0], rm = rrm[0];
        #pragma unroll
        for (int i = 1; i < 8; i++){
            mn = fminf(mn, rmn[i]); mx = fmaxf(mx, rmx[i]); rm = fmaxf(rm, rrm[i]);
        }
        bymin = mn; bymax = mx; brmax = rm;
    }
    __syncthreads();
    float ymin = bymin, ymax = bymax, rmaxb = brmax;

    if (threadIdx.x < NG){
        const float* L = labels + (size_t)(b*NG + threadIdx.x)*5;
        float l0=L[0], gcx=L[1], gcy=L[2], gw=L[3], gh=L[4];
        if ((l0+gcx+gcy+gw+gh) > 0.0f){
            float y0 = gcy - gh*0.5f, y1 = gcy + gh*0.5f;
            bool boxy = (ymax > y0) && (ymin < y1);
            bool ctry = (ymax > gcy - rmaxb) && (ymin < gcy + rmaxb);
            if (boxy || ctry){
                int p = atomicAdd(&scv, 1);
                cgt[p]  = make_float4(gcx - gw*0.5f, y0, gcx + gw*0.5f, y1);
                ccen[p] = make_float2(gcx, gcy);
            }
        }
    }
    __syncthreads();
    int cv = scv;

    bool fg = false;
    if (valid){
        for (int g = 0; g < cv; g++){
            float4 bx = cgt[g];
            float2 cn = ccen[g];
            bool ib = (xc > bx.x) && (xc < bx.z) && (yc > bx.y) && (yc < bx.w);
            bool ic = (fabsf(xc - cn.x) < r) && (fabsf(yc - cn.y) < r);
            if (ib || ic){ fg = true; break; }
        }
        g_cnt[b*NA + a] = 0;
    }

    unsigned ball = __ballot_sync(FULLM, fg);
    if (lane == 0) wcnt[wid] = __popc(ball);
    __syncthreads();
    if (threadIdx.x == 0){
        int tot = 0;
        #pragma unroll
        for (int i = 0; i < 8; i++){ wbase[i] = tot; tot += wcnt[i]; }
        blkbase = tot ? atomicAdd(&g_nfg[b], tot) : 0;
    }
    __syncthreads();

    if (fg){
        int idx = b*NA + a;
        const float* o = outputs + (size_t)idx*6;
        float2 c2 = *(const float2*)(o);
        float2 w2 = *(const float2*)(o + 2);
        float2 oc = *(const float2*)(o + 4);
        float sig_o = __fdividef(1.0f, 1.0f + __expf(-oc.x));
        float sig_c = __fdividef(1.0f, 1.0f + __expf(-oc.y));
        float clsc = -__logf(sqrtf(sig_c * sig_o) + 1e-9f);
        int pos = b*NA + blkbase + wbase[wid] + __popc(ball & ((1u << lane) - 1u));
        g_cidx[pos] = a;
        g_cbox[pos] = make_float4(c2.x - w2.x*0.5f, c2.y - w2.y*0.5f,
                                  c2.x + w2.x*0.5f, c2.y + w2.y*0.5f);
        g_cgeo[pos] = make_float4(xc, yc, r, clsc);
    }
}

// ---------------------------------------------------------------------------
// Kernel 2: 1 warp/GT; MLP=4 batched loads; EXACT warp-distributed top-10
// lists (lane k holds global k-th best) -> tight thresholds, rare insertions,
// no merge tail (winners scatter in parallel).
// ---------------------------------------------------------------------------
__global__ void k2_assign(const float* __restrict__ outputs,
                          const float* __restrict__ labels){
    int b    = blockIdx.y;
    int wid  = threadIdx.x >> 5;
    int lane = threadIdx.x & 31;
    int g    = blockIdx.x*8 + wid;
    if (g >= NG) return;

    const float* L = labels + (size_t)(b*NG + g)*5;
    float l0=L[0], gcx=L[1], gcy=L[2], gw=L[3], gh=L[4];
    if (!((l0+gcx+gcy+gw+gh) > 0.0f)) return;

    float gl = gcx - gw*0.5f, gr_ = gcx + gw*0.5f;
    float gt_ = gcy - gh*0.5f, gb = gcy + gh*0.5f;
    float garea = gw*gh;

    int nfg = g_nfg[b];
    const int*    cidx = g_cidx + b*NA;
    const float4* cbox = g_cbox + b*NA;
    const float4* cgeo = g_cgeo + b*NA;

    // distributed lists: lane k<10 holds k-th item.
    float dc = 3e38f; int di = 0x7fffffff;   // cost list, ascending lex-(cost,idx)
    float du = 0.0f;                          // iou list, descending (zeros valid)

    int nblk = (nfg + 127) >> 7;
    for (int ibk = 0; ibk < nblk; ibk++){
        int base = ibk*128 + lane;

        // batched loads (MLP=4)
        float4 bbv[4], gev[4]; int av[4]; bool actv[4];
        #pragma unroll
        for (int u = 0; u < 4; u++){
            int j = base + u*32;
            actv[u] = (j < nfg);
            if (actv[u]){
                bbv[u] = cbox[j];
                gev[u] = cgeo[j];
                av[u]  = cidx[j];
            } else av[u] = 0x7fffffff;
        }

        #pragma unroll
        for (int u = 0; u < 4; u++){
            bool act = actv[u];
            float iou = 0.0f, cost = 3e38f;
            int a = av[u];
            if (act){
                float4 bb = bbv[u];
                float4 ge = gev[u];
                float tlx = fmaxf(gl,  bb.x);
                float tly = fmaxf(gt_, bb.y);
                float brx = fminf(gr_, bb.z);
                float bry = fminf(gb,  bb.w);
                float iw = fmaxf(brx - tlx, 0.0f);
                float ih = fmaxf(bry - tly, 0.0f);
                float inter = iw*ih;
                float barea = (bb.z - bb.x)*(bb.w - bb.y);
                iou = __fdividef(inter, garea + barea - inter + 1e-12f);
                bool ib = (ge.x > gl) && (ge.x < gr_) && (ge.y > gt_) && (ge.y < gb);
                bool ic = (fabsf(ge.x - gcx) < ge.z) && (fabsf(ge.y - gcy) < ge.z);
                cost = ge.w - LN2X3*__log2f(iou + 1e-8f) + ((ib && ic) ? 0.0f : 100000.0f);
            }

            // tight thresholds = true global 10th
            float thrC = __shfl_sync(FULLM, dc, 9);
            int   ti9  = __shfl_sync(FULLM, di, 9);
            float thrI = __shfl_sync(FULLM, du, 9);

            bool doC = act && (cost < thrC || (cost == thrC && a < ti9));
            bool doI = act && (iou > thrI);
            unsigned mC = __ballot_sync(FULLM, doC);
            unsigned mI = __ballot_sync(FULLM, doI);

            while (mC){
                int src = __ffs(mC) - 1; mC &= mC - 1;
                float c = __shfl_sync(FULLM, cost, src);
                int   i = __shfl_sync(FULLM, a,    src);
                bool less = (c < dc) || (c == dc && i < di);
                unsigned m = __ballot_sync(FULLM, less);
                int first = __ffs(m) - 1;          // -1 if none -> no-op
                float pdc = __shfl_up_sync(FULLM, dc, 1);
                int   pdi = __shfl_up_sync(FULLM, di, 1);
                if (less){
                    dc = (lane == first) ? c : pdc;
                    di = (lane == first) ? i : pdi;
                }
            }
            while (mI){
                int src = __ffs(mI) - 1; mI &= mI - 1;
                float c = __shfl_sync(FULLM, iou, src);
                bool more = (c > du);
                unsigned m = __ballot_sync(FULLM, more);
                int first = __ffs(m) - 1;
                float pdu = __shfl_up_sync(FULLM, du, 1);
                if (more){
                    du = (lane == first) ? c : pdu;
                }
            }
        }
    }

    // dyn_k: descending-order sequential sum of top-10 ious (matches reference)
    float su = 0.0f;
    #pragma unroll
    for (int k = 0; k < 10; k++) su += __shfl_sync(FULLM, du, k);
    int dynk = (int)su;
    if (dynk < 1) dynk = 1;

    // winners are lanes 0..dynk-1 of the cost list; scatter in parallel
    if (lane < dynk && dc < 1e9f){
        atomicAdd(&g_cnt[b*NA + di], 1);
        const float* o = outputs + (size_t)(b*NA + di)*6;
        float bcx=o[0], bcy=o[1], bw2=o[2]*0.5f, bh2=o[3]*0.5f;
        float tlx = fmaxf(gl,  bcx-bw2), tly = fmaxf(gt_, bcy-bh2);
        float brx = fminf(gr_, bcx+bw2), bry = fminf(gb,  bcy+bh2);
        float iw = fmaxf(brx-tlx, 0.f), ih = fmaxf(bry-tly, 0.f);
        float inter = iw*ih;
        float iou = __fdividef(inter, garea + 4.f*bw2*bh2 - inter + 1e-12f);
        g_miou[b*NA + di] = iou;   // raced only when cnt>1 (then unused)
    }
}

// ---------------------------------------------------------------------------
// Kernel 3: loss over compacted fg + fused last-block final reduce.
// ---------------------------------------------------------------------------
__global__ void k3_loss(const float* __restrict__ outputs,
                        const float* __restrict__ labels,
                        float* __restrict__ out){
    __shared__ float4 sgt[NG];
    __shared__ float2 scen[NG];
    __shared__ float  sarea[NG];
    __shared__ int    snv;
    __shared__ float  ssum[256];
    __shared__ int    scnt[256];
    __shared__ bool   isLast;

    int b = blockIdx.y;
    if (threadIdx.x == 0) snv = 0;
    __syncthreads();
    if (threadIdx.x < NG){
        const float* L = labels + (size_t)(b*NG + threadIdx.x)*5;
        float l0=L[0], gcx=L[1], gcy=L[2], gw=L[3], gh=L[4];
        if ((l0+gcx+gcy+gw+gh) > 0.0f){
            int p = atomicAdd(&snv, 1);
            sgt[p]   = make_float4(gcx - gw*0.5f, gcy - gh*0.5f,
                                   gcx + gw*0.5f, gcy + gh*0.5f);
            scen[p]  = make_float2(gcx, gcy);
            sarea[p] = gw*gh;
        }
    }
    __syncthreads();
    int nv = snv;

    int nfg = g_nfg[b];
    int j = blockIdx.x*blockDim.x + threadIdx.x;
    float term = 0.0f;
    int   isfg = 0;
    if (j < nfg){
        int a   = g_cidx[b*NA + j];
        int cnt = g_cnt[b*NA + a];
        if (cnt >= 1){
            isfg = 1;
            float pred_iou;
            if (cnt == 1){
                pred_iou = g_miou[b*NA + a];
            } else {
                float4 bb = g_cbox[b*NA + j];   // corners
                float4 ge = g_cgeo[b*NA + j];
                float barea = (bb.z - bb.x)*(bb.w - bb.y);
                float bestc = 3e38f, besti = 0.0f;
                for (int g = 0; g < nv; g++){
                    float4 bx = sgt[g];
                    float2 cn = scen[g];
                    float tlx = fmaxf(bx.x, bb.x);
                    float tly = fmaxf(bx.y, bb.y);
                    float brx = fminf(bx.z, bb.z);
                    float bry = fminf(bx.w, bb.w);
                    float iw = fmaxf(brx - tlx, 0.0f);
                    float ih = fmaxf(bry - tly, 0.0f);
                    float inter = iw*ih;
                    float iou = __fdividef(inter, sarea[g] + barea - inter + 1e-12f);
                    bool ib = (ge.x > bx.x) && (ge.x < bx.z) &&
                              (ge.y > bx.y) && (ge.y < bx.w);
                    bool ic = (fabsf(ge.x - cn.x) < ge.z) && (fabsf(ge.y - cn.y) < ge.z);
                    float cost = ge.w - LN2X3*__log2f(iou + 1e-8f) +
                                 ((ib && ic) ? 0.0f : 100000.0f);
                    if (cost < bestc){ bestc = cost; besti = iou; }
                }
                pred_iou = besti;
            }
            float x = outputs[(size_t)(b*NA + a)*6 + 5];
            float sp_p = softplus(x);
            float sp_n = softplus(-x);
            term = pred_iou*sp_n + (1.0f - pred_iou)*sp_p;
        }
    }
    ssum[threadIdx.x] = term;
    scnt[threadIdx.x] = isfg;
    __syncthreads();
    for (int o = 128; o; o >>= 1){
        if (threadIdx.x < o){
            ssum[threadIdx.x] += ssum[threadIdx.x + o];
            scnt[threadIdx.x] += scnt[threadIdx.x + o];
        }
        __syncthreads();
    }
    if (threadIdx.x == 0){
        int blk = blockIdx.y*gridDim.x + blockIdx.x;
        g_psum[blk] = ssum[0];
        g_pcnt[blk] = scnt[0];
        __threadfence();
        int t = atomicAdd(&g_done, 1);
        isLast = (t == NBLK3 - 1);
    }
    __syncthreads();

    if (isLast){
        float s = 0.0f; int c = 0;
        for (int i = threadIdx.x; i < NBLK3; i += 256){ s += g_psum[i]; c += g_pcnt[i]; }
        ssum[threadIdx.x] = s; scnt[threadIdx.x] = c;
        __syncthreads();
        for (int o = 128; o; o >>= 1){
            if (threadIdx.x < o){
                ssum[threadIdx.x] += ssum[threadIdx.x+o];
                scnt[threadIdx.x] += scnt[threadIdx.x+o];
            }
            __syncthreads();
        }
        if (threadIdx.x == 0){
            float nf = (float)scnt[0];
            if (nf < 1.0f) nf = 1.0f;
            out[0] = ssum[0] / nf;
            g_done = 0;
        }
        if (threadIdx.x < NB) g_nfg[threadIdx.x] = 0;
    }
}

extern "C" void kernel_launch(void* const* d_in, const int* in_sizes, int n_in,
                              void* d_out, int out_size){
    const float* outputs = (const float*)d_in[0];  // [32, 8400, 6]
    const float* labels  = (const float*)d_in[1];  // [32, 100, 5]
    const float* xs      = (const float*)d_in[2];  // [1, 8400]
    const float* ys      = (const float*)d_in[3];  // [1, 8400]
    const float* st      = (const float*)d_in[4];  // [1, 8400]

    dim3 ganchor(33, NB);
    k1_fg_compact<<<ganchor, 256>>>(outputs, labels, xs, ys, st);
    k2_assign<<<dim3(13, NB), 256>>>(outputs, labels);
    k3_loss<<<ganchor, 256>>>(outputs, labels, (float*)d_out);
}